// round 4
// baseline (speedup 1.0000x reference)
#include <cuda_runtime.h>
#include <math.h>

#define DM 1024
#define NH 16
#define HD 64
#define NB 8
#define LQ 512
#define MROWS 4096          // NB*LQ
#define ATT_SCALE 0.125f    // 64^-0.5
#define EPS 1e-5f

// ---------------- scratch (static device globals; no allocation) -------------
__device__ float g_qin[MROWS * DM];
__device__ float g_kvin[MROWS * DM];
__device__ float g_q[MROWS * DM];
__device__ float g_k[MROWS * DM];
__device__ float g_v[MROWS * DM];
__device__ float g_att[MROWS * DM];
__device__ float g_proj[MROWS * DM];
__device__ float g_bias[LQ * LQ];

// ---------------- LayerNorm: one block per row -------------------------------
__global__ __launch_bounds__(256) void ln_kernel(const float* __restrict__ dec,
                                                 const float* __restrict__ enc,
                                                 const float* __restrict__ gamma,
                                                 const float* __restrict__ beta) {
    int row = blockIdx.x;                // 0..8191
    const float* src;
    float* dst;
    if (row < MROWS) { src = dec + (size_t)row * DM; dst = g_qin + (size_t)row * DM; }
    else             { src = enc + (size_t)(row - MROWS) * DM; dst = g_kvin + (size_t)(row - MROWS) * DM; }
    int t = threadIdx.x;                 // 256 threads, one float4 each (1024 elems)
    float4 x = ((const float4*)src)[t];
    float s  = x.x + x.y + x.z + x.w;
    float ss = x.x * x.x + x.y * x.y + x.z * x.z + x.w * x.w;
#pragma unroll
    for (int o = 16; o > 0; o >>= 1) {
        s  += __shfl_xor_sync(0xffffffffu, s, o);
        ss += __shfl_xor_sync(0xffffffffu, ss, o);
    }
    __shared__ float sb[16];
    int lane = t & 31, w = t >> 5;
    if (lane == 0) { sb[w] = s; sb[8 + w] = ss; }
    __syncthreads();
    float tot = 0.f, tot2 = 0.f;
#pragma unroll
    for (int i = 0; i < 8; i++) { tot += sb[i]; tot2 += sb[8 + i]; }
    float mean = tot * (1.0f / DM);
    float var  = tot2 * (1.0f / DM) - mean * mean;
    float inv  = rsqrtf(var + EPS);
    float4 g  = ((const float4*)gamma)[t];
    float4 bt = ((const float4*)beta)[t];
    float4 o4;
    o4.x = (x.x - mean) * inv * g.x + bt.x;
    o4.y = (x.y - mean) * inv * g.y + bt.y;
    o4.z = (x.z - mean) * inv * g.z + bt.z;
    o4.w = (x.w - mean) * inv * g.w + bt.w;
    ((float4*)dst)[t] = o4;
}

// ---------------- fp32 SGEMM: C[M,N] = A[M,K] * W[N,K]^T (+epilogues) --------
#define BM 128
#define BN 128
#define BK 16

// EPI: 0 = none, 1 = +bias[col], 2 = gate: out = sig(acc+bias)*X1 + (1-sig)*RES
template <int EPI>
__global__ __launch_bounds__(256) void sgemm_nt(const float* __restrict__ A,
                                                const float* __restrict__ W,
                                                float* __restrict__ C, int K,
                                                const float* __restrict__ bias,
                                                const float* __restrict__ X1,
                                                const float* __restrict__ RES,
                                                int N) {
    __shared__ float As[BK][BM + 4];
    __shared__ float Ws[BK][BN + 4];
    int tid  = threadIdx.x;
    int tx   = tid & 15, ty = tid >> 4;
    int brow = blockIdx.y * BM;
    int bcol = blockIdx.x * BN;
    int ar   = tid >> 2;           // 0..63
    int ac   = (tid & 3) * 4;      // 0,4,8,12

    float acc[8][8] = {};
    for (int k0 = 0; k0 < K; k0 += BK) {
#pragma unroll
        for (int i = 0; i < 2; i++) {
            int r = ar + i * 64;
            float4 av = *(const float4*)(A + (size_t)(brow + r) * K + k0 + ac);
            As[ac + 0][r] = av.x; As[ac + 1][r] = av.y;
            As[ac + 2][r] = av.z; As[ac + 3][r] = av.w;
            float4 wv = *(const float4*)(W + (size_t)(bcol + r) * K + k0 + ac);
            Ws[ac + 0][r] = wv.x; Ws[ac + 1][r] = wv.y;
            Ws[ac + 2][r] = wv.z; Ws[ac + 3][r] = wv.w;
        }
        __syncthreads();
#pragma unroll
        for (int kk = 0; kk < BK; kk++) {
            float a[8], b[8];
            *(float4*)&a[0] = *(const float4*)&As[kk][ty * 8];
            *(float4*)&a[4] = *(const float4*)&As[kk][ty * 8 + 4];
            *(float4*)&b[0] = *(const float4*)&Ws[kk][tx * 8];
            *(float4*)&b[4] = *(const float4*)&Ws[kk][tx * 8 + 4];
#pragma unroll
            for (int i = 0; i < 8; i++)
#pragma unroll
                for (int j = 0; j < 8; j++) acc[i][j] += a[i] * b[j];
        }
        __syncthreads();
    }

    int row0 = brow + ty * 8;
    int col0 = bcol + tx * 8;
#pragma unroll
    for (int i = 0; i < 8; i++) {
        size_t base = (size_t)(row0 + i) * N + col0;
#pragma unroll
        for (int jj = 0; jj < 2; jj++) {
            int j = jj * 4;
            float4 v = make_float4(acc[i][j], acc[i][j + 1], acc[i][j + 2], acc[i][j + 3]);
            if (EPI >= 1) {
                v.x += bias[col0 + j + 0];
                v.y += bias[col0 + j + 1];
                v.z += bias[col0 + j + 2];
                v.w += bias[col0 + j + 3];
            }
            if (EPI == 2) {
                float4 x1 = *(const float4*)(X1 + base + j);
                float4 rs = *(const float4*)(RES + base + j);
                float g0 = 1.f / (1.f + __expf(-v.x));
                float g1 = 1.f / (1.f + __expf(-v.y));
                float g2 = 1.f / (1.f + __expf(-v.z));
                float g3 = 1.f / (1.f + __expf(-v.w));
                v.x = g0 * x1.x + (1.f - g0) * rs.x;
                v.y = g1 * x1.y + (1.f - g1) * rs.y;
                v.z = g2 * x1.z + (1.f - g2) * rs.z;
                v.w = g3 * x1.w + (1.f - g3) * rs.w;
            }
            *(float4*)(C + base + j) = v;
        }
    }
}

// ---------------- RoPE on q and k (in place) ---------------------------------
__global__ __launch_bounds__(256) void rope_kernel() {
    const int per = MROWS * NH * (HD / 2);  // 2,097,152
    int idx = blockIdx.x * 256 + threadIdx.x;
    float* arr = (idx < per) ? g_q : g_k;
    int i = (idx < per) ? idx : idx - per;
    int d   = i & 31;
    int hl  = i >> 5;
    int h   = hl & 15;
    int row = hl >> 4;          // 0..4095
    int l   = row & (LQ - 1);
    float* p = arr + (size_t)row * DM + h * HD + d;
    float e = p[0], o = p[32];
    // inv_freq = 10000^(-d/32) = exp(-d * ln(10000)/32)
    float ang = (float)l * expf((float)d * -0.28782313662425576f);
    float sn, cs;
    sincosf(ang, &sn, &cs);
    p[0]  = e * cs - o * sn;
    p[32] = e * sn + o * cs;
}

// ---------------- temporal bias, 128x128 base bilinear-resized to 512x512 ----
__device__ __forceinline__ float tb_base(int a, int b) {
    float d = fabsf((float)(a - b));
    return expf(-d * 0.1f) - d * 0.05f;
}

__global__ __launch_bounds__(256) void bias_kernel() {
    int idx = blockIdx.x * 256 + threadIdx.x;  // 512*512
    int i = idx >> 9, j = idx & 511;
    float yc = (i + 0.5f) * 0.25f - 0.5f;
    float xc = (j + 0.5f) * 0.25f - 0.5f;
    float y0f = floorf(yc), x0f = floorf(xc);
    float fy = yc - y0f, fx = xc - x0f;
    int y0 = min(max((int)y0f, 0), 127);
    int y1 = min(max((int)y0f + 1, 0), 127);
    int x0 = min(max((int)x0f, 0), 127);
    int x1 = min(max((int)x0f + 1, 0), 127);
    float v = (1.f - fy) * ((1.f - fx) * tb_base(y0, x0) + fx * tb_base(y0, x1)) +
              fy        * ((1.f - fx) * tb_base(y1, x0) + fx * tb_base(y1, x1));
    g_bias[idx] = v;
}

// ---------------- attention: flash-style fp32, 64x64 tiles -------------------
__device__ __forceinline__ float red16_max(float v) {
    v = fmaxf(v, __shfl_xor_sync(0xffffffffu, v, 1));
    v = fmaxf(v, __shfl_xor_sync(0xffffffffu, v, 2));
    v = fmaxf(v, __shfl_xor_sync(0xffffffffu, v, 4));
    v = fmaxf(v, __shfl_xor_sync(0xffffffffu, v, 8));
    return v;
}
__device__ __forceinline__ float red16_sum(float v) {
    v += __shfl_xor_sync(0xffffffffu, v, 1);
    v += __shfl_xor_sync(0xffffffffu, v, 2);
    v += __shfl_xor_sync(0xffffffffu, v, 4);
    v += __shfl_xor_sync(0xffffffffu, v, 8);
    return v;
}

__global__ __launch_bounds__(256) void attn_kernel() {
    __shared__ float sQT[64][64];   // [d][qi], XOR-swizzled
    __shared__ float sKP[64][64];   // K: [d][kj] swizzled; reused for P^T: [kj][qi] swizzled
    __shared__ float sV[64][64];    // [kj][d], natural
    int bh = blockIdx.x;            // b*16+h
    int qt = blockIdx.y;            // 0..7
    int b = bh >> 4, h = bh & 15;
    int tid = threadIdx.x;
    int tx = tid & 15, ty = tid >> 4;
    int ty4 = ty * 4, tx4 = tx * 4;
    int r0 = tid >> 4, c4 = tid & 15;

    const float* qbase = g_q + ((size_t)(b * LQ + qt * 64)) * DM + h * HD;
#pragma unroll
    for (int it = 0; it < 4; it++) {
        int r = r0 + it * 16;
        float4 v = *(const float4*)(qbase + (size_t)r * DM + c4 * 4);
        int d0 = c4 * 4;
        sQT[d0 + 0][r ^ ((d0 + 0) & 31)] = v.x;
        sQT[d0 + 1][r ^ ((d0 + 1) & 31)] = v.y;
        sQT[d0 + 2][r ^ ((d0 + 2) & 31)] = v.z;
        sQT[d0 + 3][r ^ ((d0 + 3) & 31)] = v.w;
    }

    float o[4][4] = {};
    float m[4], l[4];
#pragma unroll
    for (int i = 0; i < 4; i++) { m[i] = -1e30f; l[i] = 0.f; }

    for (int kt = 0; kt < 8; kt++) {
        const float* kbase = g_k + ((size_t)(b * LQ + kt * 64)) * DM + h * HD;
#pragma unroll
        for (int it = 0; it < 4; it++) {
            int r = r0 + it * 16;
            float4 v = *(const float4*)(kbase + (size_t)r * DM + c4 * 4);
            int d0 = c4 * 4;
            sKP[d0 + 0][r ^ ((d0 + 0) & 31)] = v.x;
            sKP[d0 + 1][r ^ ((d0 + 1) & 31)] = v.y;
            sKP[d0 + 2][r ^ ((d0 + 2) & 31)] = v.z;
            sKP[d0 + 3][r ^ ((d0 + 3) & 31)] = v.w;
        }
        __syncthreads();

        float s[4][4] = {};
#pragma unroll 16
        for (int kk = 0; kk < 64; kk++) {
            int sw = kk & 31;
            float af[4], bf[4];
#pragma unroll
            for (int i = 0; i < 4; i++) af[i] = sQT[kk][(ty4 + i) ^ sw];
#pragma unroll
            for (int j = 0; j < 4; j++) bf[j] = sKP[kk][(tx4 + j) ^ sw];
#pragma unroll
            for (int i = 0; i < 4; i++)
#pragma unroll
                for (int j = 0; j < 4; j++) s[i][j] += af[i] * bf[j];
        }

        const float* bptr = g_bias + (size_t)(qt * 64 + ty4) * LQ + kt * 64 + tx4;
#pragma unroll
        for (int i = 0; i < 4; i++)
#pragma unroll
            for (int j = 0; j < 4; j++)
                s[i][j] = s[i][j] * ATT_SCALE + bptr[(size_t)i * LQ + j];

        float mn[4], al[4];
#pragma unroll
        for (int i = 0; i < 4; i++) {
            float rm = fmaxf(fmaxf(s[i][0], s[i][1]), fmaxf(s[i][2], s[i][3]));
            rm = red16_max(rm);
            mn[i] = fmaxf(m[i], rm);
            al[i] = __expf(m[i] - mn[i]);
        }
#pragma unroll
        for (int i = 0; i < 4; i++) {
#pragma unroll
            for (int j = 0; j < 4; j++) s[i][j] = __expf(s[i][j] - mn[i]);
            float rs = s[i][0] + s[i][1] + s[i][2] + s[i][3];
            rs = red16_sum(rs);
            l[i] = l[i] * al[i] + rs;
            m[i] = mn[i];
#pragma unroll
            for (int j = 0; j < 4; j++) o[i][j] *= al[i];
        }
        __syncthreads();   // everyone done reading sKP(K) before overwrite with P

        // store P^T (swizzled) into sKP; load V tile
#pragma unroll
        for (int j = 0; j < 4; j++) {
            int kj = tx4 + j, sw2 = kj & 31;
#pragma unroll
            for (int i = 0; i < 4; i++) sKP[kj][(ty4 + i) ^ sw2] = s[i][j];
        }
        const float* vbase = g_v + ((size_t)(b * LQ + kt * 64)) * DM + h * HD;
#pragma unroll
        for (int it = 0; it < 4; it++) {
            int r = r0 + it * 16;
            *(float4*)&sV[r][c4 * 4] = *(const float4*)(vbase + (size_t)r * DM + c4 * 4);
        }
        __syncthreads();

#pragma unroll 16
        for (int kj = 0; kj < 64; kj++) {
            int sw3 = kj & 31;
            float a2[4];
#pragma unroll
            for (int i = 0; i < 4; i++) a2[i] = sKP[kj][(ty4 + i) ^ sw3];
            float4 b4 = *(const float4*)&sV[kj][tx4];
#pragma unroll
            for (int i = 0; i < 4; i++) {
                o[i][0] += a2[i] * b4.x;
                o[i][1] += a2[i] * b4.y;
                o[i][2] += a2[i] * b4.z;
                o[i][3] += a2[i] * b4.w;
            }
        }
        __syncthreads();   // P/V consumed before next iteration's K load
    }

    float* obase = g_att + ((size_t)(b * LQ + qt * 64)) * DM + h * HD;
#pragma unroll
    for (int i = 0; i < 4; i++) {
        float inv = 1.0f / l[i];
        float4 v = make_float4(o[i][0] * inv, o[i][1] * inv, o[i][2] * inv, o[i][3] * inv);
        *(float4*)(obase + (size_t)(ty4 + i) * DM + tx4) = v;
    }
}

// ---------------- launcher ---------------------------------------------------
extern "C" void kernel_launch(void* const* d_in, const int* in_sizes, int n_in,
                              void* d_out, int out_size) {
    const float* dec    = (const float*)d_in[0];
    const float* enc    = (const float*)d_in[1];
    const float* Wqkv   = (const float*)d_in[2];
    const float* Wout   = (const float*)d_in[3];
    const float* b_out  = (const float*)d_in[4];
    const float* Wgate  = (const float*)d_in[5];
    const float* b_gate = (const float*)d_in[6];
    const float* gamma  = (const float*)d_in[7];
    const float* beta   = (const float*)d_in[8];
    float* out = (float*)d_out;

    float *qin, *kvin, *q, *k, *v, *att, *proj;
    cudaGetSymbolAddress((void**)&qin,  g_qin);
    cudaGetSymbolAddress((void**)&kvin, g_kvin);
    cudaGetSymbolAddress((void**)&q,    g_q);
    cudaGetSymbolAddress((void**)&k,    g_k);
    cudaGetSymbolAddress((void**)&v,    g_v);
    cudaGetSymbolAddress((void**)&att,  g_att);
    cudaGetSymbolAddress((void**)&proj, g_proj);

    ln_kernel<<<2 * MROWS, 256>>>(dec, enc, gamma, beta);

    dim3 gg(DM / BN, MROWS / BM);   // (8, 32)
    sgemm_nt<0><<<gg, 256>>>(qin,  Wqkv,                      q, DM, nullptr, nullptr, nullptr, DM);
    sgemm_nt<0><<<gg, 256>>>(kvin, Wqkv + (size_t)DM * DM,    k, DM, nullptr, nullptr, nullptr, DM);
    sgemm_nt<0><<<gg, 256>>>(kvin, Wqkv + (size_t)2 * DM * DM, v, DM, nullptr, nullptr, nullptr, DM);

    rope_kernel<<<(2 * MROWS * NH * (HD / 2)) / 256, 256>>>();
    bias_kernel<<<(LQ * LQ) / 256, 256>>>();

    attn_kernel<<<dim3(NB * NH, LQ / 64), 256>>>();

    sgemm_nt<1><<<gg, 256>>>(att,  Wout,  proj, DM, b_out,  nullptr, nullptr, DM);
    sgemm_nt<2><<<gg, 256>>>(proj, Wgate, out,  DM, b_gate, proj,    dec,     DM);
}

// round 9
// speedup vs baseline: 1.9908x; 1.9908x over previous
#include <cuda_runtime.h>
#include <math.h>
#include <stdint.h>

#define DM 1024
#define NH 16
#define HD 64
#define NB 8
#define LQ 512
#define MROWS 4096          // NB*LQ
#define ATT_SCALE 0.125f    // 64^-0.5
#define EPS 1e-5f

// ---------------- scratch (static device globals; no allocation) -------------
__device__ float g_qin[MROWS * DM];
__device__ float g_kvin[MROWS * DM];
__device__ float g_q[MROWS * DM];
__device__ float g_k[MROWS * DM];
__device__ float g_v[MROWS * DM];
__device__ float g_att[MROWS * DM];
__device__ float g_proj[MROWS * DM];
__device__ float g_bias[LQ * LQ];
__device__ float g_wqkv[3 * DM * DM];   // tf32-rounded weights
__device__ float g_wout[DM * DM];
__device__ float g_wgate[DM * DM];

// ---------------- helpers ----------------------------------------------------
__device__ __forceinline__ float rtf32(float x) {
    uint32_t r;
    asm("cvt.rna.tf32.f32 %0, %1;" : "=r"(r) : "f"(x));
    return __uint_as_float(r);
}
__device__ __forceinline__ uint32_t smem_u32(const void* p) {
    uint32_t a;
    asm("{ .reg .u64 t; cvta.to.shared.u64 t, %1; cvt.u32.u64 %0, t; }" : "=r"(a) : "l"(p));
    return a;
}
__device__ __forceinline__ void cpasync16(uint32_t s, const void* g) {
    asm volatile("cp.async.cg.shared.global [%0], [%1], 16;" :: "r"(s), "l"(g));
}
#define CP_COMMIT() asm volatile("cp.async.commit_group;" ::: "memory")

__device__ __forceinline__ void mma8(float* d, const uint32_t* a, const uint32_t* b) {
    asm volatile(
        "mma.sync.aligned.m16n8k8.row.col.f32.tf32.tf32.f32 "
        "{%0,%1,%2,%3}, {%4,%5,%6,%7}, {%8,%9}, {%0,%1,%2,%3};"
        : "+f"(d[0]), "+f"(d[1]), "+f"(d[2]), "+f"(d[3])
        : "r"(a[0]), "r"(a[1]), "r"(a[2]), "r"(a[3]), "r"(b[0]), "r"(b[1]));
}

// ---------------- weight convert: fp32 -> tf32-rounded copies ----------------
__global__ __launch_bounds__(256) void wcvt_kernel(const float4* __restrict__ wqkv,
                                                   const float4* __restrict__ wout,
                                                   const float4* __restrict__ wgate) {
    const int NQ = 3 * DM * DM / 4;   // 786432
    const int NO = DM * DM / 4;       // 262144
    int i = blockIdx.x * 256 + threadIdx.x;   // 0 .. NQ+2*NO-1
    float4 v; float4* dst;
    if (i < NQ)           { v = wqkv[i];            dst = (float4*)g_wqkv  + i; }
    else if (i < NQ + NO) { v = wout[i - NQ];       dst = (float4*)g_wout  + (i - NQ); }
    else                  { v = wgate[i - NQ - NO]; dst = (float4*)g_wgate + (i - NQ - NO); }
    v.x = rtf32(v.x); v.y = rtf32(v.y); v.z = rtf32(v.z); v.w = rtf32(v.w);
    *dst = v;
}

// ======================= TF32 mma.sync GEMM ==================================
// C[M,N] = A[M,K=1024] * W[N,K=1024]^T ; CTA tile 128(M) x 256(N), BK=32.
// 8 warps, 2(M) x 4(N), warp tile 64x64, mma m16n8k8.
// Inputs must be tf32-exact (pre-rounded).
// EPI: 0=plain, 1=+bias then tf32-round store, 2=gate mix.
#define GBM 128
#define GBN 256
#define GBK 32
#define ASTR 36                          // smem row stride in floats (bank-CF)
#define A_SMF (GBM * ASTR)               // 4608 floats
#define B_SMF (GBN * ASTR)               // 9216 floats
#define STG_F (A_SMF + B_SMF)            // 13824 floats
#define STG_B (STG_F * 4)                // 55296 bytes
#define NSTG 3
#define NCHK (DM / GBK)                  // 32
#define GEMM_SMEM (NSTG * STG_B)         // 165888 bytes

template <int EPI>
__global__ __launch_bounds__(256, 1) void mma_nt(const float* __restrict__ A,
                                                 const float* __restrict__ W,
                                                 float* __restrict__ C,
                                                 const float* __restrict__ bias,
                                                 const float* __restrict__ X1,
                                                 const float* __restrict__ RES) {
    extern __shared__ float smf[];
    uint32_t sbase = smem_u32(smf);
    int tid = threadIdx.x;
    int wid = tid >> 5, lane = tid & 31;
    int gid = lane >> 2, tig = lane & 3;
    int wm = wid >> 2, wn = wid & 3;           // 2 x 4 warp grid
    int brow = blockIdx.y * GBM;
    int bcol = blockIdx.x * GBN;

    const char* Arow = (const char*)(A + (size_t)brow * DM);
    const char* Wrow = (const char*)(W + (size_t)bcol * DM);

    // ---- stage loader: A[128x32] + B[256x32], rows stride 144B in smem ------
    auto load_chunk = [&](int c, int st) {
        uint32_t sA = sbase + st * STG_B;
        uint32_t sB = sA + A_SMF * 4;
        const char* Ag = Arow + (size_t)c * GBK * 4;
        const char* Bg = Wrow + (size_t)c * GBK * 4;
#pragma unroll
        for (int j = 0; j < 4; j++) {          // A: 1024 granules / 256 thr
            int gi = tid + j * 256;
            int r = gi >> 3, g = gi & 7;
            cpasync16(sA + r * 144 + g * 16, Ag + (size_t)r * (DM * 4) + g * 16);
        }
#pragma unroll
        for (int j = 0; j < 8; j++) {          // B: 2048 granules / 256 thr
            int gi = tid + j * 256;
            int r = gi >> 3, g = gi & 7;
            cpasync16(sB + r * 144 + g * 16, Bg + (size_t)r * (DM * 4) + g * 16);
        }
        CP_COMMIT();
    };

    float acc[4][8][4] = {};

    load_chunk(0, 0);
    load_chunk(1, 1);

    for (int c = 0; c < NCHK; c++) {
        int st = c % NSTG;
        if (c + 2 < NCHK) load_chunk(c + 2, (c + 2) % NSTG);
        if (c < NCHK - 2)       asm volatile("cp.async.wait_group 2;" ::: "memory");
        else if (c == NCHK - 2) asm volatile("cp.async.wait_group 1;" ::: "memory");
        else                    asm volatile("cp.async.wait_group 0;" ::: "memory");
        __syncthreads();

        const float* sA = smf + st * STG_F;
        const float* sB = sA + A_SMF;
#pragma unroll
        for (int ks = 0; ks < 4; ks++) {
            int col = 8 * ks + tig;
            uint32_t af[4][4];
#pragma unroll
            for (int i = 0; i < 4; i++) {
                int m = wm * 64 + 16 * i + gid;
                af[i][0] = __float_as_uint(sA[m * ASTR + col]);
                af[i][1] = __float_as_uint(sA[(m + 8) * ASTR + col]);
                af[i][2] = __float_as_uint(sA[m * ASTR + col + 4]);
                af[i][3] = __float_as_uint(sA[(m + 8) * ASTR + col + 4]);
            }
            uint32_t bf[8][2];
#pragma unroll
            for (int j = 0; j < 8; j++) {
                int n = wn * 64 + 8 * j + gid;
                bf[j][0] = __float_as_uint(sB[n * ASTR + col]);
                bf[j][1] = __float_as_uint(sB[n * ASTR + col + 4]);
            }
#pragma unroll
            for (int i = 0; i < 4; i++)
#pragma unroll
                for (int j = 0; j < 8; j++) mma8(acc[i][j], af[i], bf[j]);
        }
        __syncthreads();
    }

    // ---- epilogue -----------------------------------------------------------
#pragma unroll
    for (int i = 0; i < 4; i++) {
        int r0 = brow + wm * 64 + 16 * i + gid;
        int r1 = r0 + 8;
#pragma unroll
        for (int j = 0; j < 8; j++) {
            int col = bcol + wn * 64 + 8 * j + 2 * tig;
            float c0 = acc[i][j][0], c1 = acc[i][j][1];
            float c2 = acc[i][j][2], c3 = acc[i][j][3];
            if (EPI >= 1) {
                float b0 = bias[col], b1 = bias[col + 1];
                c0 += b0; c1 += b1; c2 += b0; c3 += b1;
            }
            size_t o0 = (size_t)r0 * DM + col;
            size_t o1 = (size_t)r1 * DM + col;
            if (EPI == 2) {
                float2 x0 = *(const float2*)(X1 + o0);
                float2 x1 = *(const float2*)(X1 + o1);
                float2 s0 = *(const float2*)(RES + o0);
                float2 s1 = *(const float2*)(RES + o1);
                float g0 = 1.f / (1.f + __expf(-c0));
                float g1 = 1.f / (1.f + __expf(-c1));
                float g2 = 1.f / (1.f + __expf(-c2));
                float g3 = 1.f / (1.f + __expf(-c3));
                c0 = g0 * x0.x + (1.f - g0) * s0.x;
                c1 = g1 * x0.y + (1.f - g1) * s0.y;
                c2 = g2 * x1.x + (1.f - g2) * s1.x;
                c3 = g3 * x1.y + (1.f - g3) * s1.y;
            }
            if (EPI == 1) {   // proj feeds the gate GEMM: keep it tf32-exact
                c0 = rtf32(c0); c1 = rtf32(c1); c2 = rtf32(c2); c3 = rtf32(c3);
            }
            *(float2*)(C + o0) = make_float2(c0, c1);
            *(float2*)(C + o1) = make_float2(c2, c3);
        }
    }
}

// ---------------- LayerNorm: one block per row (tf32-rounded output) ---------
__global__ __launch_bounds__(256) void ln_kernel(const float* __restrict__ dec,
                                                 const float* __restrict__ enc,
                                                 const float* __restrict__ gamma,
                                                 const float* __restrict__ beta) {
    int row = blockIdx.x;                // 0..8191
    const float* src;
    float* dst;
    if (row < MROWS) { src = dec + (size_t)row * DM; dst = g_qin + (size_t)row * DM; }
    else             { src = enc + (size_t)(row - MROWS) * DM; dst = g_kvin + (size_t)(row - MROWS) * DM; }
    int t = threadIdx.x;
    float4 x = ((const float4*)src)[t];
    float s  = x.x + x.y + x.z + x.w;
    float ss = x.x * x.x + x.y * x.y + x.z * x.z + x.w * x.w;
#pragma unroll
    for (int o = 16; o > 0; o >>= 1) {
        s  += __shfl_xor_sync(0xffffffffu, s, o);
        ss += __shfl_xor_sync(0xffffffffu, ss, o);
    }
    __shared__ float sb[16];
    int lane = t & 31, w = t >> 5;
    if (lane == 0) { sb[w] = s; sb[8 + w] = ss; }
    __syncthreads();
    float tot = 0.f, tot2 = 0.f;
#pragma unroll
    for (int i = 0; i < 8; i++) { tot += sb[i]; tot2 += sb[8 + i]; }
    float mean = tot * (1.0f / DM);
    float var  = tot2 * (1.0f / DM) - mean * mean;
    float inv  = rsqrtf(var + EPS);
    float4 g  = ((const float4*)gamma)[t];
    float4 bt = ((const float4*)beta)[t];
    float4 o4;
    o4.x = rtf32((x.x - mean) * inv * g.x + bt.x);
    o4.y = rtf32((x.y - mean) * inv * g.y + bt.y);
    o4.z = rtf32((x.z - mean) * inv * g.z + bt.z);
    o4.w = rtf32((x.w - mean) * inv * g.w + bt.w);
    ((float4*)dst)[t] = o4;
}

// ---------------- RoPE on q and k (in place) ---------------------------------
__global__ __launch_bounds__(256) void rope_kernel() {
    const int per = MROWS * NH * (HD / 2);  // 2,097,152
    int idx = blockIdx.x * 256 + threadIdx.x;
    float* arr = (idx < per) ? g_q : g_k;
    int i = (idx < per) ? idx : idx - per;
    int d   = i & 31;
    int hl  = i >> 5;
    int h   = hl & 15;
    int row = hl >> 4;          // 0..4095
    int l   = row & (LQ - 1);
    float* p = arr + (size_t)row * DM + h * HD + d;
    float e = p[0], o = p[32];
    float ang = (float)l * expf((float)d * -0.28782313662425576f);
    float sn, cs;
    sincosf(ang, &sn, &cs);
    p[0]  = e * cs - o * sn;
    p[32] = e * sn + o * cs;
}

// ---------------- temporal bias, 128x128 base bilinear-resized to 512x512 ----
__device__ __forceinline__ float tb_base(int a, int b) {
    float d = fabsf((float)(a - b));
    return expf(-d * 0.1f) - d * 0.05f;
}

__global__ __launch_bounds__(256) void bias_kernel() {
    int idx = blockIdx.x * 256 + threadIdx.x;  // 512*512
    int i = idx >> 9, j = idx & 511;
    float yc = (i + 0.5f) * 0.25f - 0.5f;
    float xc = (j + 0.5f) * 0.25f - 0.5f;
    float y0f = floorf(yc), x0f = floorf(xc);
    float fy = yc - y0f, fx = xc - x0f;
    int y0 = min(max((int)y0f, 0), 127);
    int y1 = min(max((int)y0f + 1, 0), 127);
    int x0 = min(max((int)x0f, 0), 127);
    int x1 = min(max((int)x0f + 1, 0), 127);
    float v = (1.f - fy) * ((1.f - fx) * tb_base(y0, x0) + fx * tb_base(y0, x1)) +
              fy        * ((1.f - fx) * tb_base(y1, x0) + fx * tb_base(y1, x1));
    g_bias[idx] = v;
}

// ---------------- attention: flash-style fp32, 64x64 tiles -------------------
__device__ __forceinline__ float red16_max(float v) {
    v = fmaxf(v, __shfl_xor_sync(0xffffffffu, v, 1));
    v = fmaxf(v, __shfl_xor_sync(0xffffffffu, v, 2));
    v = fmaxf(v, __shfl_xor_sync(0xffffffffu, v, 4));
    v = fmaxf(v, __shfl_xor_sync(0xffffffffu, v, 8));
    return v;
}
__device__ __forceinline__ float red16_sum(float v) {
    v += __shfl_xor_sync(0xffffffffu, v, 1);
    v += __shfl_xor_sync(0xffffffffu, v, 2);
    v += __shfl_xor_sync(0xffffffffu, v, 4);
    v += __shfl_xor_sync(0xffffffffu, v, 8);
    return v;
}

__global__ __launch_bounds__(256) void attn_kernel() {
    __shared__ float sQT[64][64];   // [d][qi], XOR-swizzled
    __shared__ float sKP[64][64];   // K: [d][kj] swizzled; reused for P^T
    __shared__ float sV[64][64];    // [kj][d], natural
    int bh = blockIdx.x;            // b*16+h
    int qt = blockIdx.y;            // 0..7
    int b = bh >> 4, h = bh & 15;
    int tid = threadIdx.x;
    int tx = tid & 15, ty = tid >> 4;
    int ty4 = ty * 4, tx4 = tx * 4;
    int r0 = tid >> 4, c4 = tid & 15;

    const float* qbase = g_q + ((size_t)(b * LQ + qt * 64)) * DM + h * HD;
#pragma unroll
    for (int it = 0; it < 4; it++) {
        int r = r0 + it * 16;
        float4 v = *(const float4*)(qbase + (size_t)r * DM + c4 * 4);
        int d0 = c4 * 4;
        sQT[d0 + 0][r ^ ((d0 + 0) & 31)] = v.x;
        sQT[d0 + 1][r ^ ((d0 + 1) & 31)] = v.y;
        sQT[d0 + 2][r ^ ((d0 + 2) & 31)] = v.z;
        sQT[d0 + 3][r ^ ((d0 + 3) & 31)] = v.w;
    }

    float o[4][4] = {};
    float m[4], l[4];
#pragma unroll
    for (int i = 0; i < 4; i++) { m[i] = -1e30f; l[i] = 0.f; }

    for (int kt = 0; kt < 8; kt++) {
        const float* kbase = g_k + ((size_t)(b * LQ + kt * 64)) * DM + h * HD;
#pragma unroll
        for (int it = 0; it < 4; it++) {
            int r = r0 + it * 16;
            float4 v = *(const float4*)(kbase + (size_t)r * DM + c4 * 4);
            int d0 = c4 * 4;
            sKP[d0 + 0][r ^ ((d0 + 0) & 31)] = v.x;
            sKP[d0 + 1][r ^ ((d0 + 1) & 31)] = v.y;
            sKP[d0 + 2][r ^ ((d0 + 2) & 31)] = v.z;
            sKP[d0 + 3][r ^ ((d0 + 3) & 31)] = v.w;
        }
        __syncthreads();

        float s[4][4] = {};
#pragma unroll 16
        for (int kk = 0; kk < 64; kk++) {
            int sw = kk & 31;
            float af[4], bf[4];
#pragma unroll
            for (int i = 0; i < 4; i++) af[i] = sQT[kk][(ty4 + i) ^ sw];
#pragma unroll
            for (int j = 0; j < 4; j++) bf[j] = sKP[kk][(tx4 + j) ^ sw];
#pragma unroll
            for (int i = 0; i < 4; i++)
#pragma unroll
                for (int j = 0; j < 4; j++) s[i][j] += af[i] * bf[j];
        }

        const float* bptr = g_bias + (size_t)(qt * 64 + ty4) * LQ + kt * 64 + tx4;
#pragma unroll
        for (int i = 0; i < 4; i++)
#pragma unroll
            for (int j = 0; j < 4; j++)
                s[i][j] = s[i][j] * ATT_SCALE + bptr[(size_t)i * LQ + j];

        float mn[4], al[4];
#pragma unroll
        for (int i = 0; i < 4; i++) {
            float rm = fmaxf(fmaxf(s[i][0], s[i][1]), fmaxf(s[i][2], s[i][3]));
            rm = red16_max(rm);
            mn[i] = fmaxf(m[i], rm);
            al[i] = __expf(m[i] - mn[i]);
        }
#pragma unroll
        for (int i = 0; i < 4; i++) {
#pragma unroll
            for (int j = 0; j < 4; j++) s[i][j] = __expf(s[i][j] - mn[i]);
            float rs = s[i][0] + s[i][1] + s[i][2] + s[i][3];
            rs = red16_sum(rs);
            l[i] = l[i] * al[i] + rs;
            m[i] = mn[i];
#pragma unroll
            for (int j = 0; j < 4; j++) o[i][j] *= al[i];
        }
        __syncthreads();

#pragma unroll
        for (int j = 0; j < 4; j++) {
            int kj = tx4 + j, sw2 = kj & 31;
#pragma unroll
            for (int i = 0; i < 4; i++) sKP[kj][(ty4 + i) ^ sw2] = s[i][j];
        }
        const float* vbase = g_v + ((size_t)(b * LQ + kt * 64)) * DM + h * HD;
#pragma unroll
        for (int it = 0; it < 4; it++) {
            int r = r0 + it * 16;
            *(float4*)&sV[r][c4 * 4] = *(const float4*)(vbase + (size_t)r * DM + c4 * 4);
        }
        __syncthreads();

#pragma unroll 16
        for (int kj = 0; kj < 64; kj++) {
            int sw3 = kj & 31;
            float a2[4];
#pragma unroll
            for (int i = 0; i < 4; i++) a2[i] = sKP[kj][(ty4 + i) ^ sw3];
            float4 b4 = *(const float4*)&sV[kj][tx4];
#pragma unroll
            for (int i = 0; i < 4; i++) {
                o[i][0] += a2[i] * b4.x;
                o[i][1] += a2[i] * b4.y;
                o[i][2] += a2[i] * b4.z;
                o[i][3] += a2[i] * b4.w;
            }
        }
        __syncthreads();
    }

    float* obase = g_att + ((size_t)(b * LQ + qt * 64)) * DM + h * HD;
#pragma unroll
    for (int i = 0; i < 4; i++) {
        float inv = 1.0f / l[i];
        // tf32-round: g_att is an mma operand downstream
        float4 v = make_float4(rtf32(o[i][0] * inv), rtf32(o[i][1] * inv),
                               rtf32(o[i][2] * inv), rtf32(o[i][3] * inv));
        *(float4*)(obase + (size_t)(ty4 + i) * DM + tx4) = v;
    }
}

// ---------------- launcher ---------------------------------------------------
extern "C" void kernel_launch(void* const* d_in, const int* in_sizes, int n_in,
                              void* d_out, int out_size) {
    const float* dec    = (const float*)d_in[0];
    const float* enc    = (const float*)d_in[1];
    const float* Wqkv   = (const float*)d_in[2];
    const float* Wout   = (const float*)d_in[3];
    const float* b_out  = (const float*)d_in[4];
    const float* Wgate  = (const float*)d_in[5];
    const float* b_gate = (const float*)d_in[6];
    const float* gamma  = (const float*)d_in[7];
    const float* beta   = (const float*)d_in[8];
    float* out = (float*)d_out;

    float *qin, *kvin, *q, *k, *v, *att, *proj, *wqkv, *wout, *wgate;
    cudaGetSymbolAddress((void**)&qin,   g_qin);
    cudaGetSymbolAddress((void**)&kvin,  g_kvin);
    cudaGetSymbolAddress((void**)&q,     g_q);
    cudaGetSymbolAddress((void**)&k,     g_k);
    cudaGetSymbolAddress((void**)&v,     g_v);
    cudaGetSymbolAddress((void**)&att,   g_att);
    cudaGetSymbolAddress((void**)&proj,  g_proj);
    cudaGetSymbolAddress((void**)&wqkv,  g_wqkv);
    cudaGetSymbolAddress((void**)&wout,  g_wout);
    cudaGetSymbolAddress((void**)&wgate, g_wgate);

    cudaFuncSetAttribute(mma_nt<0>, cudaFuncAttributeMaxDynamicSharedMemorySize, GEMM_SMEM);
    cudaFuncSetAttribute(mma_nt<1>, cudaFuncAttributeMaxDynamicSharedMemorySize, GEMM_SMEM);
    cudaFuncSetAttribute(mma_nt<2>, cudaFuncAttributeMaxDynamicSharedMemorySize, GEMM_SMEM);

    wcvt_kernel<<<(5 * DM * DM / 4) / 256, 256>>>((const float4*)Wqkv,
                                                  (const float4*)Wout,
                                                  (const float4*)Wgate);
    ln_kernel<<<2 * MROWS, 256>>>(dec, enc, gamma, beta);

    dim3 gg(DM / GBN, MROWS / GBM);   // (4, 32) = 128 CTAs
    mma_nt<0><<<gg, 256, GEMM_SMEM>>>(qin,  wqkv,                       q, nullptr, nullptr, nullptr);
    mma_nt<0><<<gg, 256, GEMM_SMEM>>>(kvin, wqkv + (size_t)DM * DM,     k, nullptr, nullptr, nullptr);
    mma_nt<0><<<gg, 256, GEMM_SMEM>>>(kvin, wqkv + (size_t)2 * DM * DM, v, nullptr, nullptr, nullptr);

    rope_kernel<<<(2 * MROWS * NH * (HD / 2)) / 256, 256>>>();
    bias_kernel<<<(LQ * LQ) / 256, 256>>>();

    attn_kernel<<<dim3(NB * NH, LQ / 64), 256>>>();

    mma_nt<1><<<gg, 256, GEMM_SMEM>>>(att,  wout,  proj, b_out,  nullptr, nullptr);
    mma_nt<2><<<gg, 256, GEMM_SMEM>>>(proj, wgate, out,  b_gate, proj,    dec);
}

// round 11
// speedup vs baseline: 3.2016x; 1.6082x over previous
#include <cuda_runtime.h>
#include <math.h>
#include <stdint.h>

#define DM 1024
#define NH 16
#define HD 64
#define NB 8
#define LQ 512
#define MROWS 4096          // NB*LQ
#define ATT_SCALE 0.125f    // 64^-0.5
#define EPS 1e-5f

// ---------------- scratch (static device globals; no allocation) -------------
__device__ float g_qin[MROWS * DM];
__device__ float g_kvin[MROWS * DM];
__device__ float g_q[MROWS * DM];
__device__ float g_k[MROWS * DM];
__device__ float g_v[MROWS * DM];
__device__ float g_att[MROWS * DM];
__device__ float g_proj[MROWS * DM];
__device__ float g_bias[LQ * LQ];

// ---------------- helpers ----------------------------------------------------
__device__ __forceinline__ float rtf32(float x) {
    uint32_t r;
    asm("cvt.rna.tf32.f32 %0, %1;" : "=r"(r) : "f"(x));
    return __uint_as_float(r);
}
__device__ __forceinline__ uint32_t smem_u32(const void* p) {
    uint32_t a;
    asm("{ .reg .u64 t; cvta.to.shared.u64 t, %1; cvt.u32.u64 %0, t; }" : "=r"(a) : "l"(p));
    return a;
}
__device__ __forceinline__ void cpasync16(uint32_t s, const void* g) {
    asm volatile("cp.async.cg.shared.global [%0], [%1], 16;" :: "r"(s), "l"(g));
}
#define CP_COMMIT() asm volatile("cp.async.commit_group;" ::: "memory")

__device__ __forceinline__ void mma8(float* d, const uint32_t* a, const uint32_t* b) {
    asm volatile(
        "mma.sync.aligned.m16n8k8.row.col.f32.tf32.tf32.f32 "
        "{%0,%1,%2,%3}, {%4,%5,%6,%7}, {%8,%9}, {%0,%1,%2,%3};"
        : "+f"(d[0]), "+f"(d[1]), "+f"(d[2]), "+f"(d[3])
        : "r"(a[0]), "r"(a[1]), "r"(a[2]), "r"(a[3]), "r"(b[0]), "r"(b[1]));
}

// ======================= TF32 mma.sync GEMM ==================================
// C[M,N] = A[M,K=1024] * W[N,K=1024]^T ; CTA tile 128(M) x 256(N), BK=32.
// 8 warps, 2(M) x 4(N), warp tile 64x64, mma m16n8k8.
// EPI: 0=plain, 1=+bias then tf32-round store, 2=gate mix.
#define GBM 128
#define GBN 256
#define GBK 32
#define ASTR 36                          // smem row stride in floats (bank-CF)
#define A_SMF (GBM * ASTR)               // 4608 floats
#define B_SMF (GBN * ASTR)               // 9216 floats
#define STG_F (A_SMF + B_SMF)            // 13824 floats
#define STG_B (STG_F * 4)                // 55296 bytes
#define NSTG 3
#define NCHK (DM / GBK)                  // 32
#define GEMM_SMEM (NSTG * STG_B)         // 165888 bytes

template <int EPI>
__global__ __launch_bounds__(256, 1) void mma_nt(const float* __restrict__ A,
                                                 const float* __restrict__ W,
                                                 float* __restrict__ C,
                                                 const float* __restrict__ bias,
                                                 const float* __restrict__ X1,
                                                 const float* __restrict__ RES) {
    extern __shared__ float smf[];
    uint32_t sbase = smem_u32(smf);
    int tid = threadIdx.x;
    int wid = tid >> 5, lane = tid & 31;
    int gid = lane >> 2, tig = lane & 3;
    int wm = wid >> 2, wn = wid & 3;           // 2 x 4 warp grid
    int brow = blockIdx.y * GBM;
    int bcol = blockIdx.x * GBN;

    const char* Arow = (const char*)(A + (size_t)brow * DM);
    const char* Wrow = (const char*)(W + (size_t)bcol * DM);

    auto load_chunk = [&](int c, int st) {
        uint32_t sA = sbase + st * STG_B;
        uint32_t sB = sA + A_SMF * 4;
        const char* Ag = Arow + (size_t)c * GBK * 4;
        const char* Bg = Wrow + (size_t)c * GBK * 4;
#pragma unroll
        for (int j = 0; j < 4; j++) {          // A: 1024 granules / 256 thr
            int gi = tid + j * 256;
            int r = gi >> 3, g = gi & 7;
            cpasync16(sA + r * 144 + g * 16, Ag + (size_t)r * (DM * 4) + g * 16);
        }
#pragma unroll
        for (int j = 0; j < 8; j++) {          // B: 2048 granules / 256 thr
            int gi = tid + j * 256;
            int r = gi >> 3, g = gi & 7;
            cpasync16(sB + r * 144 + g * 16, Bg + (size_t)r * (DM * 4) + g * 16);
        }
        CP_COMMIT();
    };

    float acc[4][8][4] = {};

    load_chunk(0, 0);
    load_chunk(1, 1);

    for (int c = 0; c < NCHK; c++) {
        int st = c % NSTG;
        if (c + 2 < NCHK) load_chunk(c + 2, (c + 2) % NSTG);
        if (c < NCHK - 2)       asm volatile("cp.async.wait_group 2;" ::: "memory");
        else if (c == NCHK - 2) asm volatile("cp.async.wait_group 1;" ::: "memory");
        else                    asm volatile("cp.async.wait_group 0;" ::: "memory");
        __syncthreads();

        const float* sA = smf + st * STG_F;
        const float* sB = sA + A_SMF;
#pragma unroll
        for (int ks = 0; ks < 4; ks++) {
            int col = 8 * ks + tig;
            uint32_t af[4][4];
#pragma unroll
            for (int i = 0; i < 4; i++) {
                int m = wm * 64 + 16 * i + gid;
                af[i][0] = __float_as_uint(sA[m * ASTR + col]);
                af[i][1] = __float_as_uint(sA[(m + 8) * ASTR + col]);
                af[i][2] = __float_as_uint(sA[m * ASTR + col + 4]);
                af[i][3] = __float_as_uint(sA[(m + 8) * ASTR + col + 4]);
            }
            uint32_t bf[8][2];
#pragma unroll
            for (int j = 0; j < 8; j++) {
                int n = wn * 64 + 8 * j + gid;
                bf[j][0] = __float_as_uint(sB[n * ASTR + col]);
                bf[j][1] = __float_as_uint(sB[n * ASTR + col + 4]);
            }
#pragma unroll
            for (int i = 0; i < 4; i++)
#pragma unroll
                for (int j = 0; j < 8; j++) mma8(acc[i][j], af[i], bf[j]);
        }
        __syncthreads();
    }

    // ---- epilogue -----------------------------------------------------------
#pragma unroll
    for (int i = 0; i < 4; i++) {
        int r0 = brow + wm * 64 + 16 * i + gid;
        int r1 = r0 + 8;
#pragma unroll
        for (int j = 0; j < 8; j++) {
            int col = bcol + wn * 64 + 8 * j + 2 * tig;
            float c0 = acc[i][j][0], c1 = acc[i][j][1];
            float c2 = acc[i][j][2], c3 = acc[i][j][3];
            if (EPI >= 1) {
                float b0 = bias[col], b1 = bias[col + 1];
                c0 += b0; c1 += b1; c2 += b0; c3 += b1;
            }
            size_t o0 = (size_t)r0 * DM + col;
            size_t o1 = (size_t)r1 * DM + col;
            if (EPI == 2) {
                float2 x0 = *(const float2*)(X1 + o0);
                float2 x1 = *(const float2*)(X1 + o1);
                float2 s0 = *(const float2*)(RES + o0);
                float2 s1 = *(const float2*)(RES + o1);
                float g0 = 1.f / (1.f + __expf(-c0));
                float g1 = 1.f / (1.f + __expf(-c1));
                float g2 = 1.f / (1.f + __expf(-c2));
                float g3 = 1.f / (1.f + __expf(-c3));
                c0 = g0 * x0.x + (1.f - g0) * s0.x;
                c1 = g1 * x0.y + (1.f - g1) * s0.y;
                c2 = g2 * x1.x + (1.f - g2) * s1.x;
                c3 = g3 * x1.y + (1.f - g3) * s1.y;
            }
            if (EPI == 1) {   // proj feeds the gate GEMM: keep it tf32-exact
                c0 = rtf32(c0); c1 = rtf32(c1); c2 = rtf32(c2); c3 = rtf32(c3);
            }
            *(float2*)(C + o0) = make_float2(c0, c1);
            *(float2*)(C + o1) = make_float2(c2, c3);
        }
    }
}

// ---------------- LayerNorm: one block per row (tf32-rounded output) ---------
__global__ __launch_bounds__(256) void ln_kernel(const float* __restrict__ dec,
                                                 const float* __restrict__ enc,
                                                 const float* __restrict__ gamma,
                                                 const float* __restrict__ beta) {
    int row = blockIdx.x;                // 0..8191
    const float* src;
    float* dst;
    if (row < MROWS) { src = dec + (size_t)row * DM; dst = g_qin + (size_t)row * DM; }
    else             { src = enc + (size_t)(row - MROWS) * DM; dst = g_kvin + (size_t)(row - MROWS) * DM; }
    int t = threadIdx.x;
    float4 x = ((const float4*)src)[t];
    float s  = x.x + x.y + x.z + x.w;
    float ss = x.x * x.x + x.y * x.y + x.z * x.z + x.w * x.w;
#pragma unroll
    for (int o = 16; o > 0; o >>= 1) {
        s  += __shfl_xor_sync(0xffffffffu, s, o);
        ss += __shfl_xor_sync(0xffffffffu, ss, o);
    }
    __shared__ float sb[16];
    int lane = t & 31, w = t >> 5;
    if (lane == 0) { sb[w] = s; sb[8 + w] = ss; }
    __syncthreads();
    float tot = 0.f, tot2 = 0.f;
#pragma unroll
    for (int i = 0; i < 8; i++) { tot += sb[i]; tot2 += sb[8 + i]; }
    float mean = tot * (1.0f / DM);
    float var  = tot2 * (1.0f / DM) - mean * mean;
    float inv  = rsqrtf(var + EPS);
    float4 g  = ((const float4*)gamma)[t];
    float4 bt = ((const float4*)beta)[t];
    float4 o4;
    o4.x = rtf32((x.x - mean) * inv * g.x + bt.x);
    o4.y = rtf32((x.y - mean) * inv * g.y + bt.y);
    o4.z = rtf32((x.z - mean) * inv * g.z + bt.z);
    o4.w = rtf32((x.w - mean) * inv * g.w + bt.w);
    ((float4*)dst)[t] = o4;
}

// ---------------- RoPE on q and k (in place) ---------------------------------
__global__ __launch_bounds__(256) void rope_kernel() {
    const int per = MROWS * NH * (HD / 2);  // 2,097,152
    int idx = blockIdx.x * 256 + threadIdx.x;
    float* arr = (idx < per) ? g_q : g_k;
    int i = (idx < per) ? idx : idx - per;
    int d   = i & 31;
    int hl  = i >> 5;
    int h   = hl & 15;
    int row = hl >> 4;          // 0..4095
    int l   = row & (LQ - 1);
    float* p = arr + (size_t)row * DM + h * HD + d;
    float e = p[0], o = p[32];
    float ang = (float)l * expf((float)d * -0.28782313662425576f);
    float sn, cs;
    sincosf(ang, &sn, &cs);
    p[0]  = rtf32(e * cs - o * sn);
    p[32] = rtf32(e * sn + o * cs);
}

// ---------------- temporal bias, 128x128 base bilinear-resized to 512x512 ----
__device__ __forceinline__ float tb_base(int a, int b) {
    float d = fabsf((float)(a - b));
    return expf(-d * 0.1f) - d * 0.05f;
}

__global__ __launch_bounds__(256) void bias_kernel() {
    int idx = blockIdx.x * 256 + threadIdx.x;  // 512*512
    int i = idx >> 9, j = idx & 511;
    float yc = (i + 0.5f) * 0.25f - 0.5f;
    float xc = (j + 0.5f) * 0.25f - 0.5f;
    float y0f = floorf(yc), x0f = floorf(xc);
    float fy = yc - y0f, fx = xc - x0f;
    int y0 = min(max((int)y0f, 0), 127);
    int y1 = min(max((int)y0f + 1, 0), 127);
    int x0 = min(max((int)x0f, 0), 127);
    int x1 = min(max((int)x0f + 1, 0), 127);
    float v = (1.f - fy) * ((1.f - fx) * tb_base(y0, x0) + fx * tb_base(y0, x1)) +
              fy        * ((1.f - fx) * tb_base(y1, x0) + fx * tb_base(y1, x1));
    g_bias[idx] = v;
}

// ============== attention: flash-style with mma.sync tf32 ====================
// CTA: one (b,h) head, 64 q-rows. 128 threads, 4 warps (16 q-rows each).
// kv loop in 64-row tiles, double-buffered cp.async.
// smem pad +4 floats -> (4*gid+tig) LDS patterns are conflict-free.
#define ATSTR 68
#define ATILE (64 * ATSTR)               // 4352 floats per 64x64 tile
#define ATT_SMEM (6 * ATILE * 4)         // Q + 2K + 2V + P = 104448 bytes

__global__ __launch_bounds__(128, 2) void attn_mma() {
    extern __shared__ float sm[];
    float* sQ = sm;                      // [64][68]
    float* sK = sm + ATILE;              // 2 stages
    float* sV = sm + 3 * ATILE;          // 2 stages
    float* sP = sm + 5 * ATILE;
    uint32_t sbase = smem_u32(sm);

    int bh = blockIdx.x, qt = blockIdx.y;
    int b = bh >> 4, h = bh & 15;
    int tid = threadIdx.x, wid = tid >> 5, lane = tid & 31;
    int gid = lane >> 2, tig = lane & 3;
    int mrow = wid * 16;

    // Q tile: 64 rows x 64 floats = 1024 granules of 16B
    const char* qg = (const char*)(g_q + ((size_t)(b * LQ + qt * 64)) * DM + h * HD);
#pragma unroll
    for (int j = 0; j < 8; j++) {
        int gi = tid + j * 128;
        int r = gi >> 4, g = gi & 15;
        cpasync16(sbase + (uint32_t)r * (ATSTR * 4) + g * 16,
                  qg + (size_t)r * (DM * 4) + g * 16);
    }
    auto load_kv = [&](int kt, int st) {
        const char* kg = (const char*)(g_k + ((size_t)(b * LQ + kt * 64)) * DM + h * HD);
        const char* vg = (const char*)(g_v + ((size_t)(b * LQ + kt * 64)) * DM + h * HD);
        uint32_t sk = sbase + (uint32_t)(1 + st) * ATILE * 4;
        uint32_t sv = sbase + (uint32_t)(3 + st) * ATILE * 4;
#pragma unroll
        for (int j = 0; j < 8; j++) {
            int gi = tid + j * 128;
            int r = gi >> 4, g = gi & 15;
            cpasync16(sk + (uint32_t)r * (ATSTR * 4) + g * 16, kg + (size_t)r * (DM * 4) + g * 16);
            cpasync16(sv + (uint32_t)r * (ATSTR * 4) + g * 16, vg + (size_t)r * (DM * 4) + g * 16);
        }
        CP_COMMIT();   // bundles the Q loads on the first call too
    };
    load_kv(0, 0);

    float o[8][4] = {};
    float m0 = -1e30f, m1 = -1e30f, l0 = 0.f, l1 = 0.f;

    for (int kt = 0; kt < 8; kt++) {
        int st = kt & 1;
        if (kt < 7) {
            load_kv(kt + 1, st ^ 1);
            asm volatile("cp.async.wait_group 1;" ::: "memory");
        } else {
            asm volatile("cp.async.wait_group 0;" ::: "memory");
        }
        __syncthreads();

        const float* Kt = sK + st * ATILE;
        const float* Vt = sV + st * ATILE;

        // ---- S = Q @ K^T (warp rows mrow..mrow+15, cols 0..63) --------------
        uint32_t af[8][4];
        int ra = (mrow + gid) * ATSTR, rb = (mrow + gid + 8) * ATSTR;
#pragma unroll
        for (int ks = 0; ks < 8; ks++) {
            int col = ks * 8 + tig;
            af[ks][0] = __float_as_uint(sQ[ra + col]);
            af[ks][1] = __float_as_uint(sQ[rb + col]);
            af[ks][2] = __float_as_uint(sQ[ra + col + 4]);
            af[ks][3] = __float_as_uint(sQ[rb + col + 4]);
        }
        float s[8][4] = {};
#pragma unroll
        for (int nb = 0; nb < 8; nb++) {
            int n = (nb * 8 + gid) * ATSTR;
#pragma unroll
            for (int ks = 0; ks < 8; ks++) {
                int col = ks * 8 + tig;
                uint32_t bf[2];
                bf[0] = __float_as_uint(Kt[n + col]);
                bf[1] = __float_as_uint(Kt[n + col + 4]);
                mma8(s[nb], af[ks], bf);
            }
        }

        // ---- scale + bias + online softmax ---------------------------------
        const float* bp = g_bias + (size_t)(qt * 64 + mrow + gid) * LQ + kt * 64;
        float nm0 = m0, nm1 = m1;
#pragma unroll
        for (int nb = 0; nb < 8; nb++) {
            int cc = nb * 8 + 2 * tig;
            float2 b0 = *(const float2*)(bp + cc);
            float2 b1 = *(const float2*)(bp + 8 * LQ + cc);
            s[nb][0] = s[nb][0] * ATT_SCALE + b0.x;
            s[nb][1] = s[nb][1] * ATT_SCALE + b0.y;
            s[nb][2] = s[nb][2] * ATT_SCALE + b1.x;
            s[nb][3] = s[nb][3] * ATT_SCALE + b1.y;
            nm0 = fmaxf(nm0, fmaxf(s[nb][0], s[nb][1]));
            nm1 = fmaxf(nm1, fmaxf(s[nb][2], s[nb][3]));
        }
        nm0 = fmaxf(nm0, __shfl_xor_sync(0xffffffffu, nm0, 1));
        nm0 = fmaxf(nm0, __shfl_xor_sync(0xffffffffu, nm0, 2));
        nm1 = fmaxf(nm1, __shfl_xor_sync(0xffffffffu, nm1, 1));
        nm1 = fmaxf(nm1, __shfl_xor_sync(0xffffffffu, nm1, 2));
        float al0 = __expf(m0 - nm0), al1 = __expf(m1 - nm1);
        m0 = nm0; m1 = nm1;
        float rs0 = 0.f, rs1 = 0.f;
#pragma unroll
        for (int nb = 0; nb < 8; nb++) {
            s[nb][0] = __expf(s[nb][0] - nm0);
            s[nb][1] = __expf(s[nb][1] - nm0);
            s[nb][2] = __expf(s[nb][2] - nm1);
            s[nb][3] = __expf(s[nb][3] - nm1);
            rs0 += s[nb][0] + s[nb][1];
            rs1 += s[nb][2] + s[nb][3];
        }
        rs0 += __shfl_xor_sync(0xffffffffu, rs0, 1);
        rs0 += __shfl_xor_sync(0xffffffffu, rs0, 2);
        rs1 += __shfl_xor_sync(0xffffffffu, rs1, 1);
        rs1 += __shfl_xor_sync(0xffffffffu, rs1, 2);
        l0 = l0 * al0 + rs0;
        l1 = l1 * al1 + rs1;
#pragma unroll
        for (int nb = 0; nb < 8; nb++) {
            o[nb][0] *= al0; o[nb][1] *= al0;
            o[nb][2] *= al1; o[nb][3] *= al1;
        }

        // ---- P -> smem (warp-private rows: only __syncwarp needed) ----------
#pragma unroll
        for (int nb = 0; nb < 8; nb++) {
            int cc = nb * 8 + 2 * tig;
            *(float2*)&sP[ra + cc] = make_float2(s[nb][0], s[nb][1]);
            *(float2*)&sP[rb + cc] = make_float2(s[nb][2], s[nb][3]);
        }
        __syncwarp();

        // ---- O += P @ V -----------------------------------------------------
        uint32_t pf[8][4];
#pragma unroll
        for (int ks = 0; ks < 8; ks++) {
            int col = ks * 8 + tig;
            pf[ks][0] = __float_as_uint(sP[ra + col]);
            pf[ks][1] = __float_as_uint(sP[rb + col]);
            pf[ks][2] = __float_as_uint(sP[ra + col + 4]);
            pf[ks][3] = __float_as_uint(sP[rb + col + 4]);
        }
#pragma unroll
        for (int nb = 0; nb < 8; nb++) {
            int n = nb * 8 + gid;
#pragma unroll
            for (int ks = 0; ks < 8; ks++) {
                uint32_t bf[2];
                bf[0] = __float_as_uint(Vt[(ks * 8 + tig) * ATSTR + n]);
                bf[1] = __float_as_uint(Vt[(ks * 8 + tig + 4) * ATSTR + n]);
                mma8(o[nb], pf[ks], bf);
            }
        }
        __syncthreads();   // stage st + sP fully consumed before next prefetch reuse
    }

    // ---- epilogue -----------------------------------------------------------
    float i0 = 1.f / l0, i1 = 1.f / l1;
    float* og = g_att + ((size_t)(b * LQ + qt * 64 + mrow + gid)) * DM + h * HD;
#pragma unroll
    for (int nb = 0; nb < 8; nb++) {
        int cc = nb * 8 + 2 * tig;
        *(float2*)(og + cc) =
            make_float2(rtf32(o[nb][0] * i0), rtf32(o[nb][1] * i0));
        *(float2*)(og + (size_t)8 * DM + cc) =
            make_float2(rtf32(o[nb][2] * i1), rtf32(o[nb][3] * i1));
    }
}

// ---------------- launcher ---------------------------------------------------
extern "C" void kernel_launch(void* const* d_in, const int* in_sizes, int n_in,
                              void* d_out, int out_size) {
    const float* dec    = (const float*)d_in[0];
    const float* enc    = (const float*)d_in[1];
    const float* Wqkv   = (const float*)d_in[2];
    const float* Wout   = (const float*)d_in[3];
    const float* b_out  = (const float*)d_in[4];
    const float* Wgate  = (const float*)d_in[5];
    const float* b_gate = (const float*)d_in[6];
    const float* gamma  = (const float*)d_in[7];
    const float* beta   = (const float*)d_in[8];
    float* out = (float*)d_out;

    float *qin, *kvin, *q, *k, *v, *att, *proj;
    cudaGetSymbolAddress((void**)&qin,   g_qin);
    cudaGetSymbolAddress((void**)&kvin,  g_kvin);
    cudaGetSymbolAddress((void**)&q,     g_q);
    cudaGetSymbolAddress((void**)&k,     g_k);
    cudaGetSymbolAddress((void**)&v,     g_v);
    cudaGetSymbolAddress((void**)&att,   g_att);
    cudaGetSymbolAddress((void**)&proj,  g_proj);

    cudaFuncSetAttribute(mma_nt<0>, cudaFuncAttributeMaxDynamicSharedMemorySize, GEMM_SMEM);
    cudaFuncSetAttribute(mma_nt<1>, cudaFuncAttributeMaxDynamicSharedMemorySize, GEMM_SMEM);
    cudaFuncSetAttribute(mma_nt<2>, cudaFuncAttributeMaxDynamicSharedMemorySize, GEMM_SMEM);
    cudaFuncSetAttribute(attn_mma,  cudaFuncAttributeMaxDynamicSharedMemorySize, ATT_SMEM);

    ln_kernel<<<2 * MROWS, 256>>>(dec, enc, gamma, beta);

    dim3 gg(DM / GBN, MROWS / GBM);   // (4, 32) = 128 CTAs
    mma_nt<0><<<gg, 256, GEMM_SMEM>>>(qin,  Wqkv,                       q, nullptr, nullptr, nullptr);
    mma_nt<0><<<gg, 256, GEMM_SMEM>>>(kvin, Wqkv + (size_t)DM * DM,     k, nullptr, nullptr, nullptr);
    mma_nt<0><<<gg, 256, GEMM_SMEM>>>(kvin, Wqkv + (size_t)2 * DM * DM, v, nullptr, nullptr, nullptr);

    rope_kernel<<<(2 * MROWS * NH * (HD / 2)) / 256, 256>>>();
    bias_kernel<<<(LQ * LQ) / 256, 256>>>();

    attn_mma<<<dim3(NB * NH, LQ / 64), 128, ATT_SMEM>>>();

    mma_nt<1><<<gg, 256, GEMM_SMEM>>>(att,  Wout,  proj, b_out,  nullptr, nullptr);
    mma_nt<2><<<gg, 256, GEMM_SMEM>>>(proj, Wgate, out,  b_gate, proj,    dec);
}